// round 16
// baseline (speedup 1.0000x reference)
#include <cuda_runtime.h>
#include <cuda_fp16.h>
#include <cstdint>

#define DIM 128
#define TILE_M 128
#define MAXV 100000
#define SH 136            // padded smem row stride in fp16 halves (272B)
#define CAP 128           // in-adjacency bucket capacity per node

// ---------------------------------------------------------------------------
// Device globals (no allocation allowed)
// ---------------------------------------------------------------------------
__device__ __align__(16) __half g_h_h[MAXV * DIM];      // fp16 dinv[v]*(emb@W)[v]
__device__ __align__(16) __half g_nodes_h[MAXV * DIM];  // fp16 final features + bias
__device__ int   g_cnt[MAXV];                           // in-degree (excl. self-loop)
__device__ int   g_adj[(size_t)MAXV * CAP];             // in-adjacency buckets (51MB)
// W transposed fp16: g_w1[n*128+k] = fp16(W[k][n])
__device__ __align__(16) __half g_w1[DIM * DIM];

// ---------------------------------------------------------------------------
// mma.sync fp16 m16n8k16 (row.col, f32 accum) + ldmatrix — base sm_100 OK
// ---------------------------------------------------------------------------
#define MMA_F16(c, a, b0, b1)                                               \
    asm volatile(                                                           \
        "mma.sync.aligned.m16n8k16.row.col.f32.f16.f16.f32 "                \
        "{%0,%1,%2,%3}, {%4,%5,%6,%7}, {%8,%9}, {%0,%1,%2,%3};"             \
        : "+f"((c)[0]), "+f"((c)[1]), "+f"((c)[2]), "+f"((c)[3])            \
        : "r"((a)[0]), "r"((a)[1]), "r"((a)[2]), "r"((a)[3]),               \
          "r"(b0), "r"(b1))

#define LDSM_X4(r0, r1, r2, r3, addr)                                       \
    asm volatile(                                                           \
        "ldmatrix.sync.aligned.m8n8.x4.shared.b16 {%0,%1,%2,%3}, [%4];"     \
        : "=r"(r0), "=r"(r1), "=r"(r2), "=r"(r3) : "r"(addr))

__device__ __forceinline__ uint32_t smem_u32(const void* p) {
    uint32_t a;
    asm("{ .reg .u64 t; cvta.to.shared.u64 t, %1; cvt.u32.u64 %0, t; }"
        : "=r"(a) : "l"(p));
    return a;
}

// ---------------------------------------------------------------------------
// prep: zero in-degree counters + transpose W to fp16
// ---------------------------------------------------------------------------
__global__ void k_prep(const float* __restrict__ W, int V) {
    int gid = blockIdx.x * blockDim.x + threadIdx.x;
    if (gid < V) g_cnt[gid] = 0;
    if (gid < DIM * DIM) {
        int k = gid >> 7;
        int n = gid & 127;
        g_w1[n * DIM + k] = __float2half_rn(W[gid]);
    }
}

// histogram + bucket scatter in one pass
__global__ void k_fill(const int* __restrict__ edge, int E) {
    int e = blockIdx.x * blockDim.x + threadIdx.x;
    if (e >= E) return;
    int src = __ldg(edge + e);          // edge_index[0]
    int dst = __ldg(edge + E + e);      // edge_index[1]
    int c = atomicAdd(&g_cnt[dst], 1);
    if (c < CAP) g_adj[(size_t)dst * CAP + c] = src;
}

// ---------------------------------------------------------------------------
// Tensor-core GEMM (mma.sync fp16, single-pass). Tile 128x128, 256 thr.
// Warp tile 32 rows x 64 cols (2 m-tiles x 8 n-tiles).
// SMEM: X1 @0 (34816), W1 @34816 (34816), dinv @69632 (512).
// Epilogue stage[128][132]f32 (67584) aliases X1+W1 (69632 bytes, dead). 
// ---------------------------------------------------------------------------
#define X1_OFF 0
#define W1_OFF (TILE_M * SH * 2)
#define DINV_OFF (W1_OFF + DIM * SH * 2)
#define GEMM_SMEM (DINV_OFF + 512)
#define STAGE_STRIDE 132

__global__ void __launch_bounds__(256, 2) k_gemm(const float* __restrict__ X, int V) {
    extern __shared__ __align__(16) unsigned char smem[];
    __half* x1 = reinterpret_cast<__half*>(smem + X1_OFF);
    __half* w1 = reinterpret_cast<__half*>(smem + W1_OFF);
    float* dinv_sh = reinterpret_cast<float*>(smem + DINV_OFF);

    const int tid = threadIdx.x;
    const int wid = tid >> 5;
    const int lane = tid & 31;
    const int row0 = blockIdx.x * TILE_M;
    const uint32_t sbase = smem_u32(smem);

    if (tid < TILE_M) {
        int r = row0 + tid;
        dinv_sh[tid] = (r < V) ? rsqrtf(1.0f + (float)g_cnt[r]) : 0.0f;
    }

    // Copy W tile into padded smem: 128 rows x 16 uint4
    {
        const uint4* s1 = reinterpret_cast<const uint4*>(g_w1);
#pragma unroll
        for (int i = 0; i < 8; i++) {
            int idx = tid + i * 256;
            int r = idx >> 4;
            int c = idx & 15;
            reinterpret_cast<uint4*>(w1 + r * SH)[c] = s1[idx];
        }
    }
    // Load X -> fp16 tile: 128 rows x 32 float4 = 4096; 16 per thread
    {
        const float4* X4 = reinterpret_cast<const float4*>(X);
#pragma unroll
        for (int i = 0; i < 16; i++) {
            int idx = tid + i * 256;
            int r = idx >> 5;
            int c4 = idx & 31;
            float4 v = make_float4(0.f, 0.f, 0.f, 0.f);
            if (row0 + r < V) v = X4[(size_t)(row0 + r) * 32 + c4];
            __half2 p0 = __floats2half2_rn(v.x, v.y);
            __half2 p1 = __floats2half2_rn(v.z, v.w);
            uint2 hp = make_uint2(*reinterpret_cast<uint32_t*>(&p0),
                                  *reinterpret_cast<uint32_t*>(&p1));
            *reinterpret_cast<uint2*>(x1 + r * SH + c4 * 4) = hp;
        }
    }
    __syncthreads();

    const int wr = (wid & 3) * 32;       // 4 row groups
    const int wc = (wid >> 2) * 64;      // 2 col groups
    const int g = lane >> 2;
    const int tg = lane & 3;

    const uint32_t a_row = (uint32_t)((wr + (lane & 15)) * SH + (lane >> 4) * 8) * 2;
    const uint32_t aoff_mt = 16 * SH * 2;
    uint32_t b_row[4];
#pragma unroll
    for (int p = 0; p < 4; p++)
        b_row[p] = (uint32_t)((wc + (2 * p + (lane >> 4)) * 8 + (lane & 7)) * SH +
                              ((lane >> 3) & 1) * 8) * 2;

    float acc[2][8][4];
#pragma unroll
    for (int mt = 0; mt < 2; mt++)
#pragma unroll
        for (int nt = 0; nt < 8; nt++)
#pragma unroll
            for (int j = 0; j < 4; j++) acc[mt][nt][j] = 0.0f;

#pragma unroll
    for (int kb = 0; kb < DIM; kb += 16) {
        const uint32_t koff = (uint32_t)kb * 2;
        uint32_t ah[2][4];
#pragma unroll
        for (int mt = 0; mt < 2; mt++) {
            LDSM_X4(ah[mt][0], ah[mt][1], ah[mt][2], ah[mt][3],
                    sbase + X1_OFF + a_row + mt * aoff_mt + koff);
        }
        uint32_t bh0[8], bh1[8];
#pragma unroll
        for (int p = 0; p < 4; p++) {
            LDSM_X4(bh0[2 * p], bh1[2 * p], bh0[2 * p + 1], bh1[2 * p + 1],
                    sbase + W1_OFF + b_row[p] + koff);
        }
#pragma unroll
        for (int nt = 0; nt < 8; nt++)
#pragma unroll
            for (int mt = 0; mt < 2; mt++)
                MMA_F16(acc[mt][nt], ah[mt], bh0[nt], bh1[nt]);
    }
    __syncthreads();   // X1/W1 become the epilogue stage

    {
        float* stage = reinterpret_cast<float*>(smem);
#pragma unroll
        for (int mt = 0; mt < 2; mt++) {
#pragma unroll
            for (int nt = 0; nt < 8; nt++) {
                int rs = wr + mt * 16 + g;
                int cs = wc + nt * 8 + 2 * tg;
                stage[rs * STAGE_STRIDE + cs]           = acc[mt][nt][0];
                stage[rs * STAGE_STRIDE + cs + 1]       = acc[mt][nt][1];
                stage[(rs + 8) * STAGE_STRIDE + cs]     = acc[mt][nt][2];
                stage[(rs + 8) * STAGE_STRIDE + cs + 1] = acc[mt][nt][3];
            }
        }
    }
    __syncthreads();

    // Coalesced fp16 store: g_h_h = fp16(dinv * D); 4096 float4 reads
    {
        const float* stage = reinterpret_cast<const float*>(smem);
#pragma unroll
        for (int i = 0; i < 16; i++) {
            int idx = tid + i * 256;
            int m = idx >> 5;
            int c4 = idx & 31;
            int row = row0 + m;
            if (row < V) {
                const float4 v = *reinterpret_cast<const float4*>(
                    stage + m * STAGE_STRIDE + c4 * 4);
                float s = dinv_sh[m];
                __half2 p0 = __floats2half2_rn(v.x * s, v.y * s);
                __half2 p1 = __floats2half2_rn(v.z * s, v.w * s);
                uint2 hp = make_uint2(*reinterpret_cast<uint32_t*>(&p0),
                                      *reinterpret_cast<uint32_t*>(&p1));
                reinterpret_cast<uint2*>(g_h_h)[(size_t)row * 32 + c4] = hp;
            }
        }
    }
}

// ---------------------------------------------------------------------------
// gather aggregation: warp per node v. Broadcast index loads (no shfl):
// all 32 lanes LDG the same adj entry -> L1 broadcast; iterations independent
// so both load levels pipeline (chain depth 2 instead of 3).
// g_nodes_h[v] = fp16( rsqrt(1+cnt)*( h[v] + sum_src h[src] ) + bias )
// ---------------------------------------------------------------------------
__global__ void __launch_bounds__(256) k_gather(const float* __restrict__ bias, int V) {
    int v = (blockIdx.x * blockDim.x + threadIdx.x) >> 5;
    int lane = threadIdx.x & 31;
    if (v >= V) return;

    int cnt_raw = g_cnt[v];
    int cnt = cnt_raw > CAP ? CAP : cnt_raw;

    const uint2* H = reinterpret_cast<const uint2*>(g_h_h);
    auto unp = [](uint2 hv, float4& f) {
        float2 a = __half22float2(*reinterpret_cast<__half2*>(&hv.x));
        float2 b = __half22float2(*reinterpret_cast<__half2*>(&hv.y));
        f.x = a.x; f.y = a.y; f.z = b.x; f.w = b.y;
    };

    float4 s0, s1 = make_float4(0.f, 0.f, 0.f, 0.f);
    unp(H[(size_t)v * 32 + lane], s0);       // self-loop term h[v]
    const int* adj = g_adj + (size_t)v * CAP;

    int i = 0;
    for (; i + 1 < cnt; i += 2) {
        int j0 = __ldg(adj + i);             // warp-uniform broadcast load
        int j1 = __ldg(adj + i + 1);
        float4 a, b;
        unp(H[(size_t)j0 * 32 + lane], a);
        unp(H[(size_t)j1 * 32 + lane], b);
        s0.x += a.x; s0.y += a.y; s0.z += a.z; s0.w += a.w;
        s1.x += b.x; s1.y += b.y; s1.z += b.z; s1.w += b.w;
    }
    if (i < cnt) {
        int sj = __ldg(adj + i);
        float4 a;
        unp(H[(size_t)sj * 32 + lane], a);
        s0.x += a.x; s0.y += a.y; s0.z += a.z; s0.w += a.w;
    }

    float dv = rsqrtf(1.0f + (float)cnt_raw);
    const float4 bv = reinterpret_cast<const float4*>(bias)[lane];
    float4 r = make_float4(fmaf(dv, s0.x + s1.x, bv.x),
                           fmaf(dv, s0.y + s1.y, bv.y),
                           fmaf(dv, s0.z + s1.z, bv.z),
                           fmaf(dv, s0.w + s1.w, bv.w));
    __half2 h01 = __floats2half2_rn(r.x, r.y);
    __half2 h23 = __floats2half2_rn(r.z, r.w);
    uint2 hp = make_uint2(*reinterpret_cast<uint32_t*>(&h01),
                          *reinterpret_cast<uint32_t*>(&h23));
    reinterpret_cast<uint2*>(g_nodes_h)[(size_t)v * 32 + lane] = hp;
}

// ---------------------------------------------------------------------------
// scoring: block = one item; 4 warps x 16 samples.
// item + sample rows fp16 (bias folded in both); accumulate fp32.
// ---------------------------------------------------------------------------
__global__ void __launch_bounds__(128) k_scores(const int* __restrict__ items,
                                                const int* __restrict__ samples,
                                                float* __restrict__ out, int S) {
    __shared__ float item_sh[DIM];
    const int b = blockIdx.x;
    const int t = threadIdx.x;

    const int item = __ldg(items + b);
    item_sh[t] = __half2float(g_nodes_h[(size_t)item * DIM + t]);
    __syncthreads();

    const int warp = t >> 5;
    const int lane = t & 31;
    const float4 iv = reinterpret_cast<const float4*>(item_sh)[lane];

    const int* samp = samples + (size_t)b * S;
    const uint2* NH = reinterpret_cast<const uint2*>(g_nodes_h);
#pragma unroll 4
    for (int i = 0; i < 16; i++) {
        int s = warp * 16 + i;
        int sidx = __ldg(samp + s);
        uint2 hv = NH[(size_t)sidx * 32 + lane];
        float2 f0 = __half22float2(*reinterpret_cast<__half2*>(&hv.x));
        float2 f1 = __half22float2(*reinterpret_cast<__half2*>(&hv.y));
        float p = iv.x * f0.x + iv.y * f0.y + iv.z * f1.x + iv.w * f1.y;
#pragma unroll
        for (int off = 16; off > 0; off >>= 1)
            p += __shfl_xor_sync(0xffffffffu, p, off);
        if (lane == 0) out[(size_t)b * S + s] = p;
    }
}

// ---------------------------------------------------------------------------
// launcher
// ---------------------------------------------------------------------------
extern "C" void kernel_launch(void* const* d_in, const int* in_sizes, int n_in,
                              void* d_out, int out_size) {
    const int*   items   = (const int*)d_in[0];
    const int*   samples = (const int*)d_in[1];
    const int*   edge    = (const int*)d_in[2];
    const float* emb     = (const float*)d_in[3];
    const float* W       = (const float*)d_in[4];
    const float* bias    = (const float*)d_in[5];
    float*       out     = (float*)d_out;

    const int B = in_sizes[0];
    const int S = in_sizes[1] / B;
    const int E = in_sizes[2] / 2;
    const int V = in_sizes[3] / DIM;

    // prep (zero counts + W fp16 transpose), adjacency build
    k_prep<<<(V + 255) / 256, 256>>>(W, V);
    k_fill<<<(E + 255) / 256, 256>>>(edge, E);

    // tensor-core GEMM (single-pass fp16, 128x128 tile), writes fp16 g_h
    cudaFuncSetAttribute(k_gemm, cudaFuncAttributeMaxDynamicSharedMemorySize, GEMM_SMEM);
    k_gemm<<<(V + TILE_M - 1) / TILE_M, 256, GEMM_SMEM>>>(emb, V);

    // gather aggregation (warp per node) -> fp16 g_nodes_h (+bias)
    k_gather<<<(V + 7) / 8, 256>>>(bias, V);

    // scoring (fp16 rows both sides)
    k_scores<<<B, 128>>>(items, samples, out, S);
}

// round 17
// speedup vs baseline: 1.0472x; 1.0472x over previous
#include <cuda_runtime.h>
#include <cuda_fp16.h>
#include <cstdint>

#define DIM 128
#define TILE_M 64
#define MAXV 100000
#define SH 136            // padded smem row stride in fp16 halves (272B)
#define CAP 128           // in-adjacency bucket capacity per node

// ---------------------------------------------------------------------------
// Device globals (no allocation allowed). g_cnt is zero on first use (static
// init) and re-zeroed by k_gather at the end of every launch sequence.
// ---------------------------------------------------------------------------
__device__ __align__(16) __half g_h_h[MAXV * DIM];      // fp16 dinv[v]*(emb@W)[v]
__device__ __align__(16) __half g_nodes_h[MAXV * DIM];  // fp16 final features + bias
__device__ int   g_cnt[MAXV];                           // in-degree (excl. self-loop)
__device__ int   g_adj[(size_t)MAXV * CAP];             // in-adjacency buckets (51MB)
__device__ __align__(16) __half g_w1[DIM * DIM];        // fp16 W^T

// ---------------------------------------------------------------------------
// mma.sync fp16 m16n8k16 (row.col, f32 accum) + ldmatrix — base sm_100 OK
// ---------------------------------------------------------------------------
#define MMA_F16(c, a, b0, b1)                                               \
    asm volatile(                                                           \
        "mma.sync.aligned.m16n8k16.row.col.f32.f16.f16.f32 "                \
        "{%0,%1,%2,%3}, {%4,%5,%6,%7}, {%8,%9}, {%0,%1,%2,%3};"             \
        : "+f"((c)[0]), "+f"((c)[1]), "+f"((c)[2]), "+f"((c)[3])            \
        : "r"((a)[0]), "r"((a)[1]), "r"((a)[2]), "r"((a)[3]),               \
          "r"(b0), "r"(b1))

#define LDSM_X4(r0, r1, r2, r3, addr)                                       \
    asm volatile(                                                           \
        "ldmatrix.sync.aligned.m8n8.x4.shared.b16 {%0,%1,%2,%3}, [%4];"     \
        : "=r"(r0), "=r"(r1), "=r"(r2), "=r"(r3) : "r"(addr))

__device__ __forceinline__ uint32_t smem_u32(const void* p) {
    uint32_t a;
    asm("{ .reg .u64 t; cvta.to.shared.u64 t, %1; cvt.u32.u64 %0, t; }"
        : "=r"(a) : "l"(p));
    return a;
}

// ---------------------------------------------------------------------------
// prep: transpose W to fp16 (cnt zeroing handled by k_gather epilogue)
// ---------------------------------------------------------------------------
__global__ void k_prep(const float* __restrict__ W) {
    int gid = blockIdx.x * blockDim.x + threadIdx.x;
    if (gid < DIM * DIM) {
        int k = gid >> 7;
        int n = gid & 127;
        g_w1[n * DIM + k] = __float2half_rn(W[gid]);
    }
}

// histogram + bucket scatter in one pass
__global__ void k_fill(const int* __restrict__ edge, int E) {
    int e = blockIdx.x * blockDim.x + threadIdx.x;
    if (e >= E) return;
    int src = __ldg(edge + e);          // edge_index[0]
    int dst = __ldg(edge + E + e);      // edge_index[1]
    int c = atomicAdd(&g_cnt[dst], 1);
    if (c < CAP) g_adj[(size_t)dst * CAP + c] = src;
}

// ---------------------------------------------------------------------------
// Tensor-core GEMM (mma.sync fp16, single-pass). Tile 64x128; 2 CTAs/SM.
// (R15 configuration — the 128-row tile variant measured slower.)
// SMEM: X1 @0 (17408), W1 @17408 (34816), dinv @52224.
// Epilogue stage[64][132]f32 (33792) aliases X1+W1 (dead after mainloop).
// ---------------------------------------------------------------------------
#define X1_OFF 0
#define W1_OFF (TILE_M * SH * 2)
#define DINV_OFF (W1_OFF + DIM * SH * 2)
#define GEMM_SMEM (DINV_OFF + 256)
#define STAGE_STRIDE 132

__global__ void __launch_bounds__(256, 2) k_gemm(const float* __restrict__ X, int V) {
    extern __shared__ __align__(16) unsigned char smem[];
    __half* x1 = reinterpret_cast<__half*>(smem + X1_OFF);
    __half* w1 = reinterpret_cast<__half*>(smem + W1_OFF);
    float* dinv_sh = reinterpret_cast<float*>(smem + DINV_OFF);

    const int tid = threadIdx.x;
    const int wid = tid >> 5;
    const int lane = tid & 31;
    const int row0 = blockIdx.x * TILE_M;
    const uint32_t sbase = smem_u32(smem);

    if (tid < TILE_M) {
        int r = row0 + tid;
        dinv_sh[tid] = (r < V) ? rsqrtf(1.0f + (float)g_cnt[r]) : 0.0f;
    }

    // Copy W tile into padded smem: 128 rows x 16 uint4
    {
        const uint4* s1 = reinterpret_cast<const uint4*>(g_w1);
#pragma unroll
        for (int i = 0; i < 8; i++) {
            int idx = tid + i * 256;
            int r = idx >> 4;
            int c = idx & 15;
            reinterpret_cast<uint4*>(w1 + r * SH)[c] = s1[idx];
        }
    }
    // Load X -> fp16 tile: 64 rows x 32 float4 = 2048; 8 per thread
    {
        const float4* X4 = reinterpret_cast<const float4*>(X);
#pragma unroll
        for (int i = 0; i < 8; i++) {
            int idx = tid + i * 256;
            int r = idx >> 5;
            int c4 = idx & 31;
            float4 v = make_float4(0.f, 0.f, 0.f, 0.f);
            if (row0 + r < V) v = X4[(size_t)(row0 + r) * 32 + c4];
            __half2 p0 = __floats2half2_rn(v.x, v.y);
            __half2 p1 = __floats2half2_rn(v.z, v.w);
            uint2 hp = make_uint2(*reinterpret_cast<uint32_t*>(&p0),
                                  *reinterpret_cast<uint32_t*>(&p1));
            *reinterpret_cast<uint2*>(x1 + r * SH + c4 * 4) = hp;
        }
    }
    __syncthreads();

    const int wr = (wid & 1) * 32;
    const int wc = (wid >> 1) * 32;
    const int g = lane >> 2;
    const int tg = lane & 3;

    const uint32_t a_row = (uint32_t)((wr + (lane & 15)) * SH + (lane >> 4) * 8) * 2;
    const uint32_t aoff_mt = 16 * SH * 2;
    uint32_t b_row[2];
#pragma unroll
    for (int p = 0; p < 2; p++)
        b_row[p] = (uint32_t)((wc + (2 * p + (lane >> 4)) * 8 + (lane & 7)) * SH +
                              ((lane >> 3) & 1) * 8) * 2;

    float acc[2][4][4];
#pragma unroll
    for (int mt = 0; mt < 2; mt++)
#pragma unroll
        for (int nt = 0; nt < 4; nt++)
#pragma unroll
            for (int j = 0; j < 4; j++) acc[mt][nt][j] = 0.0f;

#pragma unroll
    for (int kb = 0; kb < DIM; kb += 16) {
        const uint32_t koff = (uint32_t)kb * 2;
        uint32_t ah[2][4];
#pragma unroll
        for (int mt = 0; mt < 2; mt++) {
            LDSM_X4(ah[mt][0], ah[mt][1], ah[mt][2], ah[mt][3],
                    sbase + X1_OFF + a_row + mt * aoff_mt + koff);
        }
        uint32_t bh0[4], bh1[4];
#pragma unroll
        for (int p = 0; p < 2; p++) {
            LDSM_X4(bh0[2 * p], bh1[2 * p], bh0[2 * p + 1], bh1[2 * p + 1],
                    sbase + W1_OFF + b_row[p] + koff);
        }
#pragma unroll
        for (int nt = 0; nt < 4; nt++)
#pragma unroll
            for (int mt = 0; mt < 2; mt++)
                MMA_F16(acc[mt][nt], ah[mt], bh0[nt], bh1[nt]);
    }
    __syncthreads();   // X1/W1 become the epilogue stage

    {
        float* stage = reinterpret_cast<float*>(smem);
#pragma unroll
        for (int mt = 0; mt < 2; mt++) {
#pragma unroll
            for (int nt = 0; nt < 4; nt++) {
                int rs = wr + mt * 16 + g;
                int cs = wc + nt * 8 + 2 * tg;
                stage[rs * STAGE_STRIDE + cs]           = acc[mt][nt][0];
                stage[rs * STAGE_STRIDE + cs + 1]       = acc[mt][nt][1];
                stage[(rs + 8) * STAGE_STRIDE + cs]     = acc[mt][nt][2];
                stage[(rs + 8) * STAGE_STRIDE + cs + 1] = acc[mt][nt][3];
            }
        }
    }
    __syncthreads();

    // Coalesced fp16 store: g_h_h = fp16(dinv * D)
    {
        const float* stage = reinterpret_cast<const float*>(smem);
#pragma unroll
        for (int i = 0; i < 8; i++) {
            int idx = tid + i * 256;
            int m = idx >> 5;
            int c4 = idx & 31;
            int row = row0 + m;
            if (row < V) {
                const float4 v = *reinterpret_cast<const float4*>(
                    stage + m * STAGE_STRIDE + c4 * 4);
                float s = dinv_sh[m];
                __half2 p0 = __floats2half2_rn(v.x * s, v.y * s);
                __half2 p1 = __floats2half2_rn(v.z * s, v.w * s);
                uint2 hp = make_uint2(*reinterpret_cast<uint32_t*>(&p0),
                                      *reinterpret_cast<uint32_t*>(&p1));
                reinterpret_cast<uint2*>(g_h_h)[(size_t)row * 32 + c4] = hp;
            }
        }
    }
}

// ---------------------------------------------------------------------------
// gather: 2 nodes per warp, half-warp (16 lanes x uint4 = 256B) per row.
// 4 independent row-loads in flight per warp (2 nodes x 2 ILP).
// g_nodes_h[v] = fp16( rsqrt(1+cnt)*( h[v] + sum_src h[src] ) + bias )
// Also zeroes g_cnt[v] for the next graph replay (removes the prep pass).
// ---------------------------------------------------------------------------
__global__ void __launch_bounds__(256) k_gather(const float* __restrict__ bias, int V) {
    int gwarp = (blockIdx.x * blockDim.x + threadIdx.x) >> 5;
    int lane = threadIdx.x & 31;
    int v = gwarp * 2 + (lane >> 4);
    int l16 = lane & 15;
    if (v >= V) return;

    int cnt_raw = g_cnt[v];
    int cnt = cnt_raw > CAP ? CAP : cnt_raw;

    const uint4* H = reinterpret_cast<const uint4*>(g_h_h);  // 16 uint4 per row
    float s[8];
    {
        uint4 d = H[(size_t)v * 16 + l16];   // self-loop term h[v]
        float2 f;
        f = __half22float2(*reinterpret_cast<__half2*>(&d.x)); s[0] = f.x; s[1] = f.y;
        f = __half22float2(*reinterpret_cast<__half2*>(&d.y)); s[2] = f.x; s[3] = f.y;
        f = __half22float2(*reinterpret_cast<__half2*>(&d.z)); s[4] = f.x; s[5] = f.y;
        f = __half22float2(*reinterpret_cast<__half2*>(&d.w)); s[6] = f.x; s[7] = f.y;
    }
    auto add8 = [&](uint4 d) {
        float2 f;
        f = __half22float2(*reinterpret_cast<__half2*>(&d.x)); s[0] += f.x; s[1] += f.y;
        f = __half22float2(*reinterpret_cast<__half2*>(&d.y)); s[2] += f.x; s[3] += f.y;
        f = __half22float2(*reinterpret_cast<__half2*>(&d.z)); s[4] += f.x; s[5] += f.y;
        f = __half22float2(*reinterpret_cast<__half2*>(&d.w)); s[6] += f.x; s[7] += f.y;
    };

    const int* adj = g_adj + (size_t)v * CAP;
    int i = 0;
    for (; i + 1 < cnt; i += 2) {
        int j0 = __ldg(adj + i);             // uniform within half-warp
        int j1 = __ldg(adj + i + 1);
        uint4 d0 = H[(size_t)j0 * 16 + l16];
        uint4 d1 = H[(size_t)j1 * 16 + l16];
        add8(d0);
        add8(d1);
    }
    if (i < cnt) {
        int sj = __ldg(adj + i);
        add8(H[(size_t)sj * 16 + l16]);
    }

    float dv = rsqrtf(1.0f + (float)cnt_raw);
    const float4* B4 = reinterpret_cast<const float4*>(bias);
    float4 b0 = B4[l16 * 2];
    float4 b1 = B4[l16 * 2 + 1];
    float r0 = fmaf(dv, s[0], b0.x), r1 = fmaf(dv, s[1], b0.y);
    float r2 = fmaf(dv, s[2], b0.z), r3 = fmaf(dv, s[3], b0.w);
    float r4 = fmaf(dv, s[4], b1.x), r5 = fmaf(dv, s[5], b1.y);
    float r6 = fmaf(dv, s[6], b1.z), r7 = fmaf(dv, s[7], b1.w);

    __half2 h0 = __floats2half2_rn(r0, r1);
    __half2 h1 = __floats2half2_rn(r2, r3);
    __half2 h2 = __floats2half2_rn(r4, r5);
    __half2 h3 = __floats2half2_rn(r6, r7);
    uint4 hp = make_uint4(*reinterpret_cast<uint32_t*>(&h0),
                          *reinterpret_cast<uint32_t*>(&h1),
                          *reinterpret_cast<uint32_t*>(&h2),
                          *reinterpret_cast<uint32_t*>(&h3));
    reinterpret_cast<uint4*>(g_nodes_h)[(size_t)v * 16 + l16] = hp;

    if (l16 == 0) g_cnt[v] = 0;   // reset for next replay
}

// ---------------------------------------------------------------------------
// scoring: block = one item; 4 warps x 16 samples.
// item + sample rows fp16 (bias folded in both); accumulate fp32.
// ---------------------------------------------------------------------------
__global__ void __launch_bounds__(128) k_scores(const int* __restrict__ items,
                                                const int* __restrict__ samples,
                                                float* __restrict__ out, int S) {
    __shared__ float item_sh[DIM];
    const int b = blockIdx.x;
    const int t = threadIdx.x;

    const int item = __ldg(items + b);
    item_sh[t] = __half2float(g_nodes_h[(size_t)item * DIM + t]);
    __syncthreads();

    const int warp = t >> 5;
    const int lane = t & 31;
    const float4 iv = reinterpret_cast<const float4*>(item_sh)[lane];

    const int* samp = samples + (size_t)b * S;
    const uint2* NH = reinterpret_cast<const uint2*>(g_nodes_h);
#pragma unroll 4
    for (int i = 0; i < 16; i++) {
        int s = warp * 16 + i;
        int sidx = __ldg(samp + s);
        uint2 hv = NH[(size_t)sidx * 32 + lane];
        float2 f0 = __half22float2(*reinterpret_cast<__half2*>(&hv.x));
        float2 f1 = __half22float2(*reinterpret_cast<__half2*>(&hv.y));
        float p = iv.x * f0.x + iv.y * f0.y + iv.z * f1.x + iv.w * f1.y;
#pragma unroll
        for (int off = 16; off > 0; off >>= 1)
            p += __shfl_xor_sync(0xffffffffu, p, off);
        if (lane == 0) out[(size_t)b * S + s] = p;
    }
}

// ---------------------------------------------------------------------------
// launcher
// ---------------------------------------------------------------------------
extern "C" void kernel_launch(void* const* d_in, const int* in_sizes, int n_in,
                              void* d_out, int out_size) {
    const int*   items   = (const int*)d_in[0];
    const int*   samples = (const int*)d_in[1];
    const int*   edge    = (const int*)d_in[2];
    const float* emb     = (const float*)d_in[3];
    const float* W       = (const float*)d_in[4];
    const float* bias    = (const float*)d_in[5];
    float*       out     = (float*)d_out;

    const int B = in_sizes[0];
    const int S = in_sizes[1] / B;
    const int E = in_sizes[2] / 2;
    const int V = in_sizes[3] / DIM;

    // prep (W fp16 transpose only), adjacency build (cnt zeroed by last gather)
    k_prep<<<(DIM * DIM + 255) / 256, 256>>>(W);
    k_fill<<<(E + 255) / 256, 256>>>(edge, E);

    // tensor-core GEMM (single-pass fp16, 64x128 tile), writes fp16 g_h
    cudaFuncSetAttribute(k_gemm, cudaFuncAttributeMaxDynamicSharedMemorySize, GEMM_SMEM);
    k_gemm<<<(V + TILE_M - 1) / TILE_M, 256, GEMM_SMEM>>>(emb, V);

    // gather aggregation (2 nodes/warp) -> fp16 g_nodes_h (+bias); resets cnt
    int gwarps = (V + 1) / 2;
    k_gather<<<(gwarps * 32 + 255) / 256, 256>>>(bias, V);

    // scoring (fp16 rows both sides)
    k_scores<<<B, 128>>>(items, samples, out, S);
}